// round 3
// baseline (speedup 1.0000x reference)
#include <cuda_runtime.h>
#include <cuda_bf16.h>
#include <cstdint>

#define BB 128
#define SS 128
#define II 300
#define HH 1024
#define G4 4096
#define MTOT (BB*SS)          // 16384

// Scratch (static device arrays: allocation-free rule)
__device__ float g_Gin[(size_t)MTOT * G4];   // [S][B][4H] input-side gate pre-activations (256 MB)
__device__ float g_hs[(size_t)SS * BB * HH]; // [S][B][H] hidden states (64 MB)
__device__ unsigned g_bar_count;
__device__ unsigned g_bar_gen;

__device__ __forceinline__ uint32_t f2t(float f){
    uint32_t r; asm("cvt.rna.tf32.f32 %0, %1;" : "=r"(r) : "f"(f)); return r;
}
__device__ __forceinline__ void mma_tf32(float* c, const uint32_t* a, uint32_t b0, uint32_t b1){
    asm volatile("mma.sync.aligned.m16n8k8.row.col.f32.tf32.tf32.f32 "
        "{%0,%1,%2,%3}, {%4,%5,%6,%7}, {%8,%9}, {%0,%1,%2,%3};\n"
        : "+f"(c[0]), "+f"(c[1]), "+f"(c[2]), "+f"(c[3])
        : "r"(a[0]), "r"(a[1]), "r"(a[2]), "r"(a[3]), "r"(b0), "r"(b1));
}
__device__ __forceinline__ float sigmoidf_(float x){ return 1.f/(1.f + __expf(-x)); }
__device__ __forceinline__ float tanhf_(float x){
    float e = __expf(-2.f*fabsf(x));
    float t = (1.f - e)/(1.f + e);
    return x < 0.f ? -t : t;
}

// ---------------------------------------------------------------------------
// Kernel 1: Gin[t][b][:] = embed_W[x[b][t]] @ W_ih^T + (b_ih + b_hh)
// M = S*B = 16384 (m = t*128 + b), N = 4096, K = 300 (padded to 304)
// CTA tile 64x64, 4 warps (each 16x64), tf32 mma m16n8k8.
// ---------------------------------------------------------------------------
__global__ void __launch_bounds__(128) k_input_gemm(
    const int* __restrict__ x, const float* __restrict__ embW,
    const float* __restrict__ W_ih, const float* __restrict__ b_ih,
    const float* __restrict__ b_hh)
{
    __shared__ int      toks[64];
    __shared__ uint32_t As[64*12];   // stride 12 -> conflict-free frag loads
    __shared__ uint32_t Bs[64*12];
    const int tid = threadIdx.x, lane = tid & 31, warp = tid >> 5;
    const int gid = lane >> 2, tig = lane & 3;
    const int m0 = blockIdx.y * 64, n0 = blockIdx.x * 64;

    if (tid < 64){
        int m = m0 + tid;
        int t = m >> 7, b = m & 127;
        toks[tid] = x[b*SS + t];          // x[b][t]
    }
    __syncthreads();

    float acc[8][4];
    #pragma unroll
    for (int i=0;i<8;i++){ acc[i][0]=acc[i][1]=acc[i][2]=acc[i][3]=0.f; }

    const int li = tid >> 1;           // row 0..63
    const int lk = (tid & 1) * 4;      // 0 or 4

    for (int k0 = 0; k0 < 304; k0 += 8){
        int kg = k0 + lk;
        float4 va = make_float4(0.f,0.f,0.f,0.f), vb = va;
        if (kg < II){  // I=300 is a multiple of 4 -> float4 always in-bounds & aligned
            va = *(const float4*)(embW + (size_t)toks[li]*II + kg);
            vb = *(const float4*)(W_ih + (size_t)(n0+li)*II + kg);
        }
        As[li*12+lk+0]=f2t(va.x); As[li*12+lk+1]=f2t(va.y);
        As[li*12+lk+2]=f2t(va.z); As[li*12+lk+3]=f2t(va.w);
        Bs[li*12+lk+0]=f2t(vb.x); Bs[li*12+lk+1]=f2t(vb.y);
        Bs[li*12+lk+2]=f2t(vb.z); Bs[li*12+lk+3]=f2t(vb.w);
        __syncthreads();

        uint32_t a[4];
        int mr = warp*16;
        a[0] = As[(mr+gid  )*12 + tig  ];
        a[1] = As[(mr+gid+8)*12 + tig  ];
        a[2] = As[(mr+gid  )*12 + tig+4];
        a[3] = As[(mr+gid+8)*12 + tig+4];
        #pragma unroll
        for (int nt=0; nt<8; nt++){
            uint32_t b0v = Bs[(nt*8+gid)*12 + tig  ];
            uint32_t b1v = Bs[(nt*8+gid)*12 + tig+4];
            mma_tf32(acc[nt], a, b0v, b1v);
        }
        __syncthreads();
    }

    #pragma unroll
    for (int nt=0; nt<8; nt++){
        int n = n0 + nt*8 + 2*tig;
        float bias0 = b_ih[n]   + b_hh[n];
        float bias1 = b_ih[n+1] + b_hh[n+1];
        int mA = m0 + warp*16 + gid;
        *(float2*)(g_Gin + (size_t)mA    *G4 + n) = make_float2(acc[nt][0]+bias0, acc[nt][1]+bias1);
        *(float2*)(g_Gin + (size_t)(mA+8)*G4 + n) = make_float2(acc[nt][2]+bias0, acc[nt][3]+bias1);
    }
}

// ---------------------------------------------------------------------------
// Kernel 2: persistent LSTM recurrence.
// 128 CTAs x 128 threads. CTA ct owns hidden units [ct*8, ct*8+8) -> 32 gate
// rows of W_hh cached in SMEM as tf32 for the whole kernel. Cell state in regs.
// Per step: gates = Gin[t] + h_{t-1} @ Whh_slice^T (tf32 mma), activations,
// write h slice, grid barrier.
// ---------------------------------------------------------------------------
#define WS_STRIDE 1028   // 1024 + 4 pad: bank = (4*row + k) % 32 -> conflict-free
#define HS_STRIDE 36     // 32 + 4 pad
#define SMEM_B_BYTES ((32*WS_STRIDE + 128*HS_STRIDE)*4)

__global__ void __launch_bounds__(128) k_lstm(const float* __restrict__ W_hh)
{
    extern __shared__ uint32_t shm[];
    uint32_t* Ws = shm;                    // [32][WS_STRIDE] tf32 weights
    uint32_t* Hs = shm + 32*WS_STRIDE;     // [128][HS_STRIDE] tf32 h chunk

    const int tid = threadIdx.x, lane = tid & 31, warp = tid >> 5;
    const int gid = lane >> 2, tig = lane & 3;
    const int ct = blockIdx.x;
    const int u0 = ct * 8;

    // Load & convert W_hh slice once. Local row r = gate*8 + j.
    for (int idx = tid; idx < 32*1024; idx += 128){
        int r = idx >> 10, k = idx & 1023;
        int g = r >> 3, j = r & 7;
        Ws[r*WS_STRIDE + k] = f2t(W_hh[(size_t)(g*HH + u0 + j)*HH + k]);
    }

    __shared__ unsigned sgen0;
    if (tid == 0) sgen0 = *(volatile unsigned*)&g_bar_gen;
    __syncthreads();
    const unsigned gen0 = sgen0;

    float cst[8];                              // cell state: 4 batch rows x 2 units
    #pragma unroll
    for (int i=0;i<8;i++) cst[i] = 0.f;

    int mlist[4];
    #pragma unroll
    for (int mi=0; mi<4; mi++) mlist[mi] = warp*32 + (mi>>1)*16 + gid + (mi&1)*8;
    const int jj = 2*tig;                      // unit pair this lane owns

    for (int t = 0; t < SS; t++){
        float acc[2][4][4];
        #pragma unroll
        for (int a1=0;a1<2;a1++)
            #pragma unroll
            for (int a2=0;a2<4;a2++)
                #pragma unroll
                for (int a3=0;a3<4;a3++) acc[a1][a2][a3] = 0.f;

        if (t > 0){
            const float* hprev = g_hs + (size_t)(t-1)*BB*HH;
            for (int kc = 0; kc < HH; kc += 32){
                #pragma unroll
                for (int i=0;i<32;i++){       // coalesced: 4096 elems, 32/thread
                    int idx = i*128 + tid;
                    int m = idx >> 5, c = idx & 31;
                    Hs[m*HS_STRIDE + c] = f2t(hprev[(size_t)m*HH + kc + c]);
                }
                __syncthreads();
                #pragma unroll
                for (int ks = 0; ks < 32; ks += 8){
                    uint32_t a0[4], a1[4];
                    int mr = warp*32;
                    a0[0]=Hs[(mr+gid   )*HS_STRIDE + ks+tig  ];
                    a0[1]=Hs[(mr+gid+8 )*HS_STRIDE + ks+tig  ];
                    a0[2]=Hs[(mr+gid   )*HS_STRIDE + ks+tig+4];
                    a0[3]=Hs[(mr+gid+8 )*HS_STRIDE + ks+tig+4];
                    a1[0]=Hs[(mr+16+gid  )*HS_STRIDE + ks+tig  ];
                    a1[1]=Hs[(mr+16+gid+8)*HS_STRIDE + ks+tig  ];
                    a1[2]=Hs[(mr+16+gid  )*HS_STRIDE + ks+tig+4];
                    a1[3]=Hs[(mr+16+gid+8)*HS_STRIDE + ks+tig+4];
                    #pragma unroll
                    for (int nt=0; nt<4; nt++){
                        uint32_t b0v = Ws[(nt*8+gid)*WS_STRIDE + kc+ks+tig  ];
                        uint32_t b1v = Ws[(nt*8+gid)*WS_STRIDE + kc+ks+tig+4];
                        mma_tf32(acc[0][nt], a0, b0v, b1v);
                        mma_tf32(acc[1][nt], a1, b0v, b1v);
                    }
                }
                __syncthreads();
            }
        }

        // Epilogue: gates of unit j sit at same slot of n-tiles 0..3 (i,f,g,o).
        const float* gin  = g_Gin + (size_t)t*BB*G4;
        float*       hout = g_hs  + (size_t)t*BB*HH;
        #pragma unroll
        for (int mi=0; mi<4; mi++){
            int m  = mlist[mi];
            int mt = mi >> 1, pos = mi & 1;
            const float* gb = gin + (size_t)m*G4 + u0 + jj;
            float2 gi = *(const float2*)(gb         );
            float2 gf = *(const float2*)(gb +   HH  );
            float2 gg = *(const float2*)(gb + 2*HH  );
            float2 go = *(const float2*)(gb + 3*HH  );
            float iv0 = acc[mt][0][pos*2+0] + gi.x, iv1 = acc[mt][0][pos*2+1] + gi.y;
            float fv0 = acc[mt][1][pos*2+0] + gf.x, fv1 = acc[mt][1][pos*2+1] + gf.y;
            float gv0 = acc[mt][2][pos*2+0] + gg.x, gv1 = acc[mt][2][pos*2+1] + gg.y;
            float ov0 = acc[mt][3][pos*2+0] + go.x, ov1 = acc[mt][3][pos*2+1] + go.y;
            float c0 = sigmoidf_(fv0)*cst[mi*2+0] + sigmoidf_(iv0)*tanhf_(gv0);
            float c1 = sigmoidf_(fv1)*cst[mi*2+1] + sigmoidf_(iv1)*tanhf_(gv1);
            cst[mi*2+0] = c0; cst[mi*2+1] = c1;
            float h0 = sigmoidf_(ov0)*tanhf_(c0);
            float h1 = sigmoidf_(ov1)*tanhf_(c1);
            *(float2*)(hout + (size_t)m*HH + u0 + jj) = make_float2(h0, h1);
        }

        // Grid barrier (skip after last step; stream order covers kernel 3).
        if (t < SS-1){
            __threadfence();                 // release h writes to device scope
            __syncthreads();
            if (tid == 0){
                unsigned prev = atomicAdd(&g_bar_count, 1u);
                if (prev == gridDim.x - 1){
                    atomicExch(&g_bar_count, 0u);
                    __threadfence();
                    atomicAdd(&g_bar_gen, 1u);
                } else {
                    unsigned target = gen0 + (unsigned)(t+1);
                    while ((int)(*(volatile unsigned*)&g_bar_gen - target) < 0) {}
                }
                __threadfence();             // acquire side
            }
            __syncthreads();
        }
    }
}

// ---------------------------------------------------------------------------
// Kernel 3: out[b*S+t][:] = valid ? hs[t][b] @ lin_W^T + lin_b : (1, 0)
// One warp per output row.
// ---------------------------------------------------------------------------
__global__ void __launch_bounds__(256) k_output(
    const int* __restrict__ lengths, const float* __restrict__ lin_W,
    const float* __restrict__ lin_b, float* __restrict__ out)
{
    int row = blockIdx.x * 8 + (threadIdx.x >> 5);
    if (row >= MTOT) return;
    int lane = threadIdx.x & 31;
    int b = row >> 7, t = row & 127;      // row = b*S + t
    float2 res;
    if (t < lengths[b]){
        const float* h = g_hs + ((size_t)t*BB + b)*HH;
        float s0 = 0.f, s1 = 0.f;
        #pragma unroll 8
        for (int k = lane; k < HH; k += 32){
            float hv = h[k];
            s0 += hv * lin_W[k];
            s1 += hv * lin_W[HH + k];
        }
        #pragma unroll
        for (int off = 16; off > 0; off >>= 1){
            s0 += __shfl_down_sync(0xffffffffu, s0, off);
            s1 += __shfl_down_sync(0xffffffffu, s1, off);
        }
        res = make_float2(s0 + lin_b[0], s1 + lin_b[1]);
    } else {
        res = make_float2(1.f, 0.f);
    }
    if (lane == 0) *(float2*)(out + (size_t)row*2) = res;
}

// ---------------------------------------------------------------------------
extern "C" void kernel_launch(void* const* d_in, const int* in_sizes, int n_in,
                              void* d_out, int out_size)
{
    const int*   x       = (const int*)  d_in[0];
    const int*   lengths = (const int*)  d_in[1];
    const float* embW    = (const float*)d_in[2];
    const float* W_ih    = (const float*)d_in[3];
    const float* W_hh    = (const float*)d_in[4];
    const float* b_ih    = (const float*)d_in[5];
    const float* b_hh    = (const float*)d_in[6];
    const float* lin_W   = (const float*)d_in[7];
    const float* lin_b   = (const float*)d_in[8];
    float* out = (float*)d_out;

    cudaFuncSetAttribute(k_lstm, cudaFuncAttributeMaxDynamicSharedMemorySize, SMEM_B_BYTES);

    dim3 gA(G4/64, MTOT/64);   // 64 x 256 CTAs
    k_input_gemm<<<gA, 128>>>(x, embW, W_ih, b_ih, b_hh);
    k_lstm<<<128, 128, SMEM_B_BYTES>>>(W_hh);
    k_output<<<(MTOT+7)/8, 256>>>(lengths, lin_W, lin_b, out);
}

// round 4
// speedup vs baseline: 1.7740x; 1.7740x over previous
#include <cuda_runtime.h>
#include <cuda_bf16.h>
#include <cstdint>

#define BB 128
#define SS 128
#define II 300
#define HH 1024
#define G4 4096
#define MTOT (BB*SS)          // 16384

// Scratch (static device arrays: allocation-free rule)
__device__ float g_Gin[(size_t)MTOT * G4];              // [S][B][4H] permuted gate pre-acts
__device__ __nv_bfloat16 g_hs_bf[(size_t)SS * BB * HH]; // [S][B][H] hidden states (bf16)
__device__ unsigned g_bar_count;
__device__ unsigned g_bar_gen;

__device__ __forceinline__ uint32_t f2b2(float lo, float hi){
    __nv_bfloat162 v = __floats2bfloat162_rn(lo, hi);
    return *(uint32_t*)&v;
}
__device__ __forceinline__ void mma_bf16(float* c, const uint32_t* a, uint32_t b0, uint32_t b1){
    asm volatile("mma.sync.aligned.m16n8k16.row.col.f32.bf16.bf16.f32 "
        "{%0,%1,%2,%3}, {%4,%5,%6,%7}, {%8,%9}, {%0,%1,%2,%3};\n"
        : "+f"(c[0]), "+f"(c[1]), "+f"(c[2]), "+f"(c[3])
        : "r"(a[0]), "r"(a[1]), "r"(a[2]), "r"(a[3]), "r"(b0), "r"(b1));
}
__device__ __forceinline__ float sigmoidf_(float x){ return 1.f/(1.f + __expf(-x)); }
__device__ __forceinline__ float tanhf_(float x){
    float e = __expf(-2.f*fabsf(x));
    float t = (1.f - e)/(1.f + e);
    return x < 0.f ? -t : t;
}
// Gate-permuted column: within a CTA's 32-col block, lane layout puts all 4
// gates of a unit into one lane.  n = g*1024 + u  ->  ct*32 + nl
__device__ __forceinline__ int permcol(int n){
    int g = n >> 10, u = n & 1023;
    int ct = u >> 3, j = u & 7;
    return ct*32 + ((j>>2)<<4) + ((g>>1)<<3) + ((j&3)<<1) + (g&1);
}

__device__ __forceinline__ void cp_async16(uint32_t s, const void* g){
    asm volatile("cp.async.ca.shared.global [%0], [%1], 16;\n" :: "r"(s), "l"(g) : "memory");
}
__device__ __forceinline__ void cp_commit(){ asm volatile("cp.async.commit_group;\n" ::: "memory"); }
__device__ __forceinline__ void cp_wait1(){ asm volatile("cp.async.wait_group 1;\n" ::: "memory"); }
__device__ __forceinline__ void cp_wait0(){ asm volatile("cp.async.wait_group 0;\n" ::: "memory"); }

// ---------------------------------------------------------------------------
// Kernel 1: Gin[t][b][perm] = embed_W[x[b][t]] @ W_ih^T + (b_ih + b_hh)
// M=16384 (m = t*128+b), N=4096, K=300 (19 k16 blocks). bf16 m16n8k16.
// CTA 64x64, 4 warps; register prefetch of next k-tile.
// ---------------------------------------------------------------------------
#define AST 12   // As row stride in 32-bit words (24 bf16)
__global__ void __launch_bounds__(128) k_input_gemm(
    const int* __restrict__ x, const float* __restrict__ embW,
    const float* __restrict__ W_ih, const float* __restrict__ b_ih,
    const float* __restrict__ b_hh)
{
    __shared__ int      toks[64];
    __shared__ uint32_t As[64*AST];
    __shared__ uint32_t Bs[64*AST];
    const int tid = threadIdx.x, lane = tid & 31, warp = tid >> 5;
    const int gid = lane >> 2, tig = lane & 3;
    const int m0 = blockIdx.y * 64, n0 = blockIdx.x * 64;

    if (tid < 64){
        int m = m0 + tid;
        int t = m >> 7, b = m & 127;
        toks[tid] = x[b*SS + t];
    }
    __syncthreads();

    float acc[8][4];
    #pragma unroll
    for (int i=0;i<8;i++){ acc[i][0]=acc[i][1]=acc[i][2]=acc[i][3]=0.f; }

    const int li = tid >> 1;           // row 0..63
    const int lk = (tid & 1) * 8;      // k offset 0 or 8
    const size_t arow = (size_t)toks[li]*II;
    const size_t brow = (size_t)(n0+li)*II;

    float4 va0, va1, vb0, vb1;
    {
        int kg = lk;
        va0 = (kg   < II) ? *(const float4*)(embW + arow + kg  ) : make_float4(0,0,0,0);
        va1 = (kg+4 < II) ? *(const float4*)(embW + arow + kg+4) : make_float4(0,0,0,0);
        vb0 = (kg   < II) ? *(const float4*)(W_ih + brow + kg  ) : make_float4(0,0,0,0);
        vb1 = (kg+4 < II) ? *(const float4*)(W_ih + brow + kg+4) : make_float4(0,0,0,0);
    }

    for (int kb = 0; kb < 19; kb++){
        int wo = li*AST + (lk>>1);
        As[wo+0]=f2b2(va0.x,va0.y); As[wo+1]=f2b2(va0.z,va0.w);
        As[wo+2]=f2b2(va1.x,va1.y); As[wo+3]=f2b2(va1.z,va1.w);
        Bs[wo+0]=f2b2(vb0.x,vb0.y); Bs[wo+1]=f2b2(vb0.z,vb0.w);
        Bs[wo+2]=f2b2(vb1.x,vb1.y); Bs[wo+3]=f2b2(vb1.z,vb1.w);
        __syncthreads();

        if (kb < 18){
            int kg = (kb+1)*16 + lk;
            va0 = (kg   < II) ? *(const float4*)(embW + arow + kg  ) : make_float4(0,0,0,0);
            va1 = (kg+4 < II) ? *(const float4*)(embW + arow + kg+4) : make_float4(0,0,0,0);
            vb0 = (kg   < II) ? *(const float4*)(W_ih + brow + kg  ) : make_float4(0,0,0,0);
            vb1 = (kg+4 < II) ? *(const float4*)(W_ih + brow + kg+4) : make_float4(0,0,0,0);
        }

        uint32_t a[4];
        int mr = warp*16;
        a[0] = As[(mr+gid  )*AST + tig  ];
        a[1] = As[(mr+gid+8)*AST + tig  ];
        a[2] = As[(mr+gid  )*AST + tig+4];
        a[3] = As[(mr+gid+8)*AST + tig+4];
        #pragma unroll
        for (int nt=0; nt<8; nt++){
            uint32_t b0v = Bs[(nt*8+gid)*AST + tig  ];
            uint32_t b1v = Bs[(nt*8+gid)*AST + tig+4];
            mma_bf16(acc[nt], a, b0v, b1v);
        }
        __syncthreads();
    }

    #pragma unroll
    for (int nt=0; nt<8; nt++){
        int n  = n0 + nt*8 + 2*tig;
        float bias0 = b_ih[n]   + b_hh[n];
        float bias1 = b_ih[n+1] + b_hh[n+1];
        int p0 = permcol(n), p1 = permcol(n+1);
        int mA = m0 + warp*16 + gid;
        float* r0 = g_Gin + (size_t)mA    *G4;
        float* r1 = g_Gin + (size_t)(mA+8)*G4;
        r0[p0] = acc[nt][0]+bias0; r0[p1] = acc[nt][1]+bias1;
        r1[p0] = acc[nt][2]+bias0; r1[p1] = acc[nt][3]+bias1;
    }
}

// ---------------------------------------------------------------------------
// Kernel 2: persistent LSTM recurrence, bf16 m16n8k16.
// 128 CTAs x 256 threads. CTA ct owns units [ct*8, ct*8+8) -> 32 gate rows of
// W_hh resident in SMEM as bf16 (perm-ordered). h streamed in CK=256 chunks
// via double-buffered cp.async. Cell state in registers.
// ---------------------------------------------------------------------------
#define CK   256
#define NCH  (HH/CK)          // 4 chunks/step
#define KPW  516              // Ws row stride, 32-bit words (1032 bf16)
#define HSW  132              // Hs row stride, 32-bit words (264 bf16); 132%32=4
#define WS_WORDS (32*KPW)     // 16512
#define HS_WORDS (128*HSW)    // 16896
#define SMEM_LSTM ((WS_WORDS + 2*HS_WORDS)*4)   // 201216 B

__global__ void __launch_bounds__(256) k_lstm(const float* __restrict__ W_hh)
{
    extern __shared__ uint32_t shm[];
    uint32_t* Ws   = shm;
    uint32_t* Hbuf[2] = { shm + WS_WORDS, shm + WS_WORDS + HS_WORDS };

    const int tid = threadIdx.x, lane = tid & 31, warp = tid >> 5;
    const int gid = lane >> 2, tig = lane & 3;
    const int mg = warp & 3, ng = warp >> 2;     // m-group (32 rows), n-group (2 n-tiles)
    const int ct = blockIdx.x;
    const int u0 = ct * 8;
    const int j  = ng*4 + tig;                   // the unit this lane owns

    // Load W_hh slice once, bf16-pair packed, rows in perm order:
    // local row r: j=(r>>4)*4+((r>>1)&3), g=((r>>3)&1)*2+(r&1)
    for (int idx = tid; idx < 32*512; idx += 256){
        int r = idx >> 9, kw = idx & 511;
        int jj_ = ((r>>4)<<2) + ((r>>1)&3);
        int gg_ = (((r>>3)&1)<<1) + (r&1);
        const float* src = W_hh + (size_t)(gg_*HH + u0 + jj_)*HH + 2*kw;
        Ws[r*KPW + kw] = f2b2(src[0], src[1]);
    }

    __shared__ unsigned sgen0;
    if (tid == 0) sgen0 = *(volatile unsigned*)&g_bar_gen;
    __syncthreads();
    const unsigned gen0 = sgen0;

    float cst[4];                                // cell state: 4 m-rows, 1 unit
    #pragma unroll
    for (int i=0;i<4;i++) cst[i] = 0.f;

    const int mr = 32*mg;
    const uint32_t hb_base[2] = {
        (uint32_t)__cvta_generic_to_shared(Hbuf[0]),
        (uint32_t)__cvta_generic_to_shared(Hbuf[1]) };

    for (int t = 0; t < SS; t++){
        float acc[2][2][4];
        #pragma unroll
        for (int a1=0;a1<2;a1++)
            #pragma unroll
            for (int a2=0;a2<2;a2++)
                #pragma unroll
                for (int a3=0;a3<4;a3++) acc[a1][a2][a3] = 0.f;

        if (t > 0){
            const __nv_bfloat16* hprev = g_hs_bf + (size_t)(t-1)*BB*HH;

            // issue chunk 0
            {
                #pragma unroll
                for (int i=0;i<16;i++){
                    int seg = i*256 + tid;            // 4096 segs of 16B
                    int row = seg >> 5, s16 = seg & 31;
                    cp_async16(hb_base[0] + (uint32_t)(row*HSW*4 + s16*16),
                               hprev + (size_t)row*HH + s16*8);
                }
                cp_commit();
            }

            for (int c = 0; c < NCH; c++){
                if (c+1 < NCH){
                    #pragma unroll
                    for (int i=0;i<16;i++){
                        int seg = i*256 + tid;
                        int row = seg >> 5, s16 = seg & 31;
                        cp_async16(hb_base[(c+1)&1] + (uint32_t)(row*HSW*4 + s16*16),
                                   hprev + (size_t)row*HH + (c+1)*CK + s16*8);
                    }
                    cp_commit();
                    cp_wait1();
                } else {
                    cp_wait0();
                }
                __syncthreads();

                const uint32_t* Hb = Hbuf[c&1];
                const int kws = c*(CK/2);            // Ws word offset for this chunk
                #pragma unroll
                for (int s = 0; s < CK/16; s++){
                    const int bw = s*8;
                    uint32_t a0[4], a1[4];
                    a0[0]=Hb[(mr+gid   )*HSW + bw+tig  ];
                    a0[1]=Hb[(mr+gid+8 )*HSW + bw+tig  ];
                    a0[2]=Hb[(mr+gid   )*HSW + bw+tig+4];
                    a0[3]=Hb[(mr+gid+8 )*HSW + bw+tig+4];
                    a1[0]=Hb[(mr+16+gid  )*HSW + bw+tig  ];
                    a1[1]=Hb[(mr+16+gid+8)*HSW + bw+tig  ];
                    a1[2]=Hb[(mr+16+gid  )*HSW + bw+tig+4];
                    a1[3]=Hb[(mr+16+gid+8)*HSW + bw+tig+4];
                    #pragma unroll
                    for (int nt=0; nt<2; nt++){
                        int nrow = (2*ng + nt)*8 + gid;
                        uint32_t b0v = Ws[nrow*KPW + kws + bw + tig  ];
                        uint32_t b1v = Ws[nrow*KPW + kws + bw + tig+4];
                        mma_bf16(acc[0][nt], a0, b0v, b1v);
                        mma_bf16(acc[1][nt], a1, b0v, b1v);
                    }
                }
                __syncthreads();
            }
        }

        // Epilogue: lane owns unit j for 4 m-rows. Gin permuted cols:
        //  (i,f) at ct*32 + ng*16 + 2tig, (g,o) at +8.
        const float* gin  = g_Gin + (size_t)t*BB*G4 + ct*32 + ng*16 + 2*tig;
        __nv_bfloat16* hout = g_hs_bf + (size_t)t*BB*HH + u0 + j;
        #pragma unroll
        for (int mi=0; mi<4; mi++){
            int mt = mi >> 1, hi = mi & 1;       // hi: 0 -> row gid, 1 -> row gid+8
            int m  = mr + 16*mt + gid + 8*hi;
            const float* gp = gin + (size_t)m*G4;
            float2 fif = *(const float2*)(gp    );
            float2 fgo = *(const float2*)(gp + 8);
            float iv = acc[mt][0][2*hi+0] + fif.x;
            float fv = acc[mt][0][2*hi+1] + fif.y;
            float gv = acc[mt][1][2*hi+0] + fgo.x;
            float ov = acc[mt][1][2*hi+1] + fgo.y;
            float cv = sigmoidf_(fv)*cst[mi] + sigmoidf_(iv)*tanhf_(gv);
            cst[mi] = cv;
            float hv = sigmoidf_(ov)*tanhf_(cv);
            hout[(size_t)m*HH] = __float2bfloat16(hv);
        }

        if (t < SS-1){
            __threadfence();
            __syncthreads();
            if (tid == 0){
                unsigned prev = atomicAdd(&g_bar_count, 1u);
                if (prev == gridDim.x - 1){
                    atomicExch(&g_bar_count, 0u);
                    __threadfence();
                    atomicAdd(&g_bar_gen, 1u);
                } else {
                    unsigned target = gen0 + (unsigned)(t+1);
                    while ((int)(*(volatile unsigned*)&g_bar_gen - target) < 0) {}
                }
                __threadfence();
            }
            __syncthreads();
        }
    }
}

// ---------------------------------------------------------------------------
// Kernel 3: out[b*S+t][:] = valid ? hs[t][b] @ lin_W^T + lin_b : (1, 0)
// One warp per output row; h is bf16.
// ---------------------------------------------------------------------------
__global__ void __launch_bounds__(256) k_output(
    const int* __restrict__ lengths, const float* __restrict__ lin_W,
    const float* __restrict__ lin_b, float* __restrict__ out)
{
    int row = blockIdx.x * 8 + (threadIdx.x >> 5);
    if (row >= MTOT) return;
    int lane = threadIdx.x & 31;
    int b = row >> 7, t = row & 127;      // row = b*S + t
    float2 res;
    if (t < lengths[b]){
        const __nv_bfloat162* h2 =
            (const __nv_bfloat162*)(g_hs_bf + ((size_t)t*BB + b)*HH);
        float s0 = 0.f, s1 = 0.f;
        #pragma unroll 4
        for (int k2 = lane; k2 < HH/2; k2 += 32){
            float2 hv = __bfloat1622float2(h2[k2]);
            s0 += hv.x * lin_W[2*k2]     + hv.y * lin_W[2*k2+1];
            s1 += hv.x * lin_W[HH+2*k2]  + hv.y * lin_W[HH+2*k2+1];
        }
        #pragma unroll
        for (int off = 16; off > 0; off >>= 1){
            s0 += __shfl_down_sync(0xffffffffu, s0, off);
            s1 += __shfl_down_sync(0xffffffffu, s1, off);
        }
        res = make_float2(s0 + lin_b[0], s1 + lin_b[1]);
    } else {
        res = make_float2(1.f, 0.f);
    }
    if (lane == 0) *(float2*)(out + (size_t)row*2) = res;
}

// ---------------------------------------------------------------------------
extern "C" void kernel_launch(void* const* d_in, const int* in_sizes, int n_in,
                              void* d_out, int out_size)
{
    const int*   x       = (const int*)  d_in[0];
    const int*   lengths = (const int*)  d_in[1];
    const float* embW    = (const float*)d_in[2];
    const float* W_ih    = (const float*)d_in[3];
    const float* W_hh    = (const float*)d_in[4];
    const float* b_ih    = (const float*)d_in[5];
    const float* b_hh    = (const float*)d_in[6];
    const float* lin_W   = (const float*)d_in[7];
    const float* lin_b   = (const float*)d_in[8];
    float* out = (float*)d_out;

    cudaFuncSetAttribute(k_lstm, cudaFuncAttributeMaxDynamicSharedMemorySize, SMEM_LSTM);

    dim3 gA(G4/64, MTOT/64);   // 64 x 256 CTAs
    k_input_gemm<<<gA, 128>>>(x, embW, W_ih, b_ih, b_hh);
    k_lstm<<<128, 256, SMEM_LSTM>>>(W_hh);
    k_output<<<(MTOT+7)/8, 256>>>(lengths, lin_W, lin_b, out);
}

// round 6
// speedup vs baseline: 2.4241x; 1.3664x over previous
#include <cuda_runtime.h>
#include <cuda_bf16.h>
#include <cstdint>

#define BB 128
#define SS 128
#define II 300
#define HH 1024
#define G4 4096
#define MTOT (BB*SS)          // 16384

// Scratch (static device arrays: allocation-free rule)
__device__ float g_Gin[(size_t)MTOT * G4];              // [S][B][4H] permuted gate pre-acts
__device__ __nv_bfloat16 g_hs_bf[(size_t)SS * BB * HH]; // [S][B][H] hidden states (bf16)
__device__ unsigned g_bar_count;
__device__ unsigned g_bar_gen;

__device__ __forceinline__ uint32_t f2b2(float lo, float hi){
    __nv_bfloat162 v = __floats2bfloat162_rn(lo, hi);
    return *(uint32_t*)&v;
}
__device__ __forceinline__ void mma_bf16(float* c, const uint32_t* a, uint32_t b0, uint32_t b1){
    asm volatile("mma.sync.aligned.m16n8k16.row.col.f32.bf16.bf16.f32 "
        "{%0,%1,%2,%3}, {%4,%5,%6,%7}, {%8,%9}, {%0,%1,%2,%3};\n"
        : "+f"(c[0]), "+f"(c[1]), "+f"(c[2]), "+f"(c[3])
        : "r"(a[0]), "r"(a[1]), "r"(a[2]), "r"(a[3]), "r"(b0), "r"(b1));
}
__device__ __forceinline__ void ldsm4(uint32_t* r, uint32_t addr){
    asm volatile("ldmatrix.sync.aligned.m8n8.x4.shared.b16 {%0,%1,%2,%3}, [%4];"
        : "=r"(r[0]), "=r"(r[1]), "=r"(r[2]), "=r"(r[3]) : "r"(addr));
}
__device__ __forceinline__ void ldsm2(uint32_t* r, uint32_t addr){
    asm volatile("ldmatrix.sync.aligned.m8n8.x2.shared.b16 {%0,%1}, [%2];"
        : "=r"(r[0]), "=r"(r[1]) : "r"(addr));
}
__device__ __forceinline__ float sigmoidf_(float x){ return 1.f/(1.f + __expf(-x)); }
__device__ __forceinline__ float tanhf_(float x){
    float e = __expf(-2.f*fabsf(x));
    float t = (1.f - e)/(1.f + e);
    return x < 0.f ? -t : t;
}
// Gate-permuted column: n = g*1024 + u  ->  ct*32 + j_hi*16 + g_hi*8 + j_lo*2 + g_lo
__device__ __forceinline__ int permcol(int n){
    int g = n >> 10, u = n & 1023;
    int ct = u >> 3, j = u & 7;
    return ct*32 + ((j>>2)<<4) + ((g>>1)<<3) + ((j&3)<<1) + (g&1);
}

__device__ __forceinline__ void cp_async16(uint32_t s, const void* g){
    asm volatile("cp.async.ca.shared.global [%0], [%1], 16;\n" :: "r"(s), "l"(g) : "memory");
}
__device__ __forceinline__ void cp_commit(){ asm volatile("cp.async.commit_group;\n" ::: "memory"); }
__device__ __forceinline__ void cp_wait1(){ asm volatile("cp.async.wait_group 1;\n" ::: "memory"); }
__device__ __forceinline__ void cp_wait0(){ asm volatile("cp.async.wait_group 0;\n" ::: "memory"); }

// ---------------------------------------------------------------------------
// Kernel 1: Gin[t][b][perm] = embed_W[x[b][t]] @ W_ih^T + (b_ih + b_hh)
// M=16384 (m = t*128+b), N=4096, K=300 (19 k16 blocks). bf16 m16n8k16.
// CTA tile 128x64, 8 warps (warp = 16 m-rows x 64 cols), register prefetch,
// ldmatrix fragment loads.
// ---------------------------------------------------------------------------
#define AST 12   // smem row stride in 32-bit words (24 bf16; 48B = 3x16B)
__global__ void __launch_bounds__(256) k_input_gemm(
    const int* __restrict__ x, const float* __restrict__ embW,
    const float* __restrict__ W_ih, const float* __restrict__ b_ih,
    const float* __restrict__ b_hh)
{
    __shared__ int      toks[128];
    __shared__ uint32_t As[128*AST];
    __shared__ uint32_t Bs[64*AST];
    const int tid = threadIdx.x, lane = tid & 31, warp = tid >> 5;
    const int gid = lane >> 2, tig = lane & 3;
    const int m0 = blockIdx.y * 128, n0 = blockIdx.x * 64;

    if (tid < 128){
        int m = m0 + tid;
        int t = m >> 7, b = m & 127;
        toks[tid] = x[b*SS + t];
    }
    __syncthreads();

    float acc[8][4];
    #pragma unroll
    for (int i=0;i<8;i++){ acc[i][0]=acc[i][1]=acc[i][2]=acc[i][3]=0.f; }

    // loaders
    const int rowA = tid >> 1, lkA = (tid & 1) * 8;    // 128 rows, 8 floats/thread
    const int rowB = tid >> 2, lkB = (tid & 3) * 4;    // 64 rows, 4 floats/thread
    const size_t arow = (size_t)toks[rowA]*II;
    const size_t brow = (size_t)(n0+rowB)*II;

    float4 va0, va1, vb0;
    {
        int kg = lkA;
        va0 = (kg   < II) ? *(const float4*)(embW + arow + kg  ) : make_float4(0,0,0,0);
        va1 = (kg+4 < II) ? *(const float4*)(embW + arow + kg+4) : make_float4(0,0,0,0);
        int kb_ = lkB;
        vb0 = (kb_  < II) ? *(const float4*)(W_ih + brow + kb_ ) : make_float4(0,0,0,0);
    }

    // per-lane ldmatrix addresses (constant across kb)
    uint32_t asb = (uint32_t)__cvta_generic_to_shared(As);
    uint32_t bsb = (uint32_t)__cvta_generic_to_shared(Bs);
    const int rowoff = (lane&7) + ((lane>>3)&1)*8;
    uint32_t aAddr = asb + (uint32_t)(((warp*16 + rowoff)*AST + ((lane>>4)&1)*4)*4);
    uint32_t bAddr[4];
    {
        int mi_ = lane >> 3;
        int ntl = mi_ >> 1, kh = mi_ & 1;
        #pragma unroll
        for (int p=0;p<4;p++)
            bAddr[p] = bsb + (uint32_t)((((p*2+ntl)*8 + (lane&7))*AST + kh*4)*4);
    }

    for (int kb = 0; kb < 19; kb++){
        {
            int wa = rowA*AST + (lkA>>1);
            As[wa+0]=f2b2(va0.x,va0.y); As[wa+1]=f2b2(va0.z,va0.w);
            As[wa+2]=f2b2(va1.x,va1.y); As[wa+3]=f2b2(va1.z,va1.w);
            int wb = rowB*AST + (lkB>>1);
            Bs[wb+0]=f2b2(vb0.x,vb0.y); Bs[wb+1]=f2b2(vb0.z,vb0.w);
        }
        __syncthreads();

        if (kb < 18){
            int kg = (kb+1)*16 + lkA;
            va0 = (kg   < II) ? *(const float4*)(embW + arow + kg  ) : make_float4(0,0,0,0);
            va1 = (kg+4 < II) ? *(const float4*)(embW + arow + kg+4) : make_float4(0,0,0,0);
            int kb_ = (kb+1)*16 + lkB;
            vb0 = (kb_  < II) ? *(const float4*)(W_ih + brow + kb_ ) : make_float4(0,0,0,0);
        }

        uint32_t a[4];
        ldsm4(a, aAddr);
        #pragma unroll
        for (int p=0; p<4; p++){
            uint32_t b[4];
            ldsm4(b, bAddr[p]);
            mma_bf16(acc[2*p  ], a, b[0], b[1]);
            mma_bf16(acc[2*p+1], a, b[2], b[3]);
        }
        __syncthreads();
    }

    #pragma unroll
    for (int nt=0; nt<8; nt++){
        int n  = n0 + nt*8 + 2*tig;
        float bias0 = b_ih[n]   + b_hh[n];
        float bias1 = b_ih[n+1] + b_hh[n+1];
        int p0 = permcol(n), p1 = permcol(n+1);
        int mA = m0 + warp*16 + gid;
        float* r0 = g_Gin + (size_t)mA    *G4;
        float* r1 = g_Gin + (size_t)(mA+8)*G4;
        r0[p0] = acc[nt][0]+bias0; r0[p1] = acc[nt][1]+bias1;
        r1[p0] = acc[nt][2]+bias0; r1[p1] = acc[nt][3]+bias1;
    }
}

// ---------------------------------------------------------------------------
// Kernel 2: persistent LSTM recurrence, bf16 m16n8k16 + ldmatrix.
// 128 CTAs x 256 threads. CTA ct owns units [ct*8, ct*8+8) -> 32 perm-ordered
// gate rows of W_hh resident in SMEM (bf16). h streamed in CK=256 chunks via
// double-buffered cp.async. Gin tile prefetched into smem one barrier early.
// h written via smem stage -> coalesced STG.128.
// ---------------------------------------------------------------------------
#define CK   256
#define NCH  (HH/CK)            // 4
#define KPW  516                // Ws row stride (words); 516%32=4 -> LDSM conflict-free
#define HSW  132                // Hs row stride (words); 132%32=4
#define GSTR 36                 // Gin smem row stride (words); 144B per row
#define WS_WORDS   (32*KPW)     // 16512
#define HB_WORDS   (128*HSW)    // 16896
#define GIN_WORDS  (128*GSTR)   // 4608
#define STG_WORDS  512          // 128 rows x 8 bf16
#define OFF_HB0  WS_WORDS
#define OFF_HB1  (WS_WORDS + HB_WORDS)
#define OFF_GIN  (WS_WORDS + 2*HB_WORDS)
#define OFF_STG  (OFF_GIN + GIN_WORDS)
#define SMEM_LSTM ((OFF_STG + STG_WORDS)*4)   // 221696 B

__global__ void __launch_bounds__(256) k_lstm(const float* __restrict__ W_hh)
{
    extern __shared__ uint32_t shm[];
    uint32_t* Ws   = shm;
    float*    GinF = (float*)(shm + OFF_GIN);
    __nv_bfloat16* Stage = (__nv_bfloat16*)(shm + OFF_STG);

    const int tid = threadIdx.x, lane = tid & 31, warp = tid >> 5;
    const int gid = lane >> 2, tig = lane & 3;
    const int mg = warp & 3, ng = warp >> 2;     // m-group (32 rows), n-group (2 n-tiles)
    const int ct = blockIdx.x;
    const int u0 = ct * 8;
    const int j  = ng*4 + tig;                   // unit this lane owns

    const uint32_t sbase = (uint32_t)__cvta_generic_to_shared(shm);
    const uint32_t ginb  = sbase + OFF_GIN*4;
    const uint32_t stgb_unused = 0; (void)stgb_unused;
    const uint32_t hbb[2] = { sbase + OFF_HB0*4, sbase + OFF_HB1*4 };

    // Prefetch Gin tile for t=0 (overlaps with weight load).
    {
        const float* gsrc = g_Gin + (size_t)ct*32;
        #pragma unroll
        for (int i=0;i<4;i++){
            int seg = i*256 + tid;
            int row = seg >> 3, s16 = seg & 7;
            cp_async16(ginb + (uint32_t)(row*(GSTR*4) + s16*16),
                       gsrc + (size_t)row*G4 + s16*4);
        }
        cp_commit();
    }

    // Load W_hh slice once, bf16-pair packed, rows in perm order.
    for (int idx = tid; idx < 32*512; idx += 256){
        int r = idx >> 9, kw = idx & 511;
        int jj_ = ((r>>4)<<2) + ((r>>1)&3);
        int gg_ = (((r>>3)&1)<<1) + (r&1);
        const float* src = W_hh + (size_t)(gg_*HH + u0 + jj_)*HH + 2*kw;
        Ws[r*KPW + kw] = f2b2(src[0], src[1]);
    }

    __shared__ unsigned sgen0;
    if (tid == 0) sgen0 = *(volatile unsigned*)&g_bar_gen;
    __syncthreads();
    const unsigned gen0 = sgen0;

    // per-lane ldmatrix addresses
    const int rowoff = (lane&7) + ((lane>>3)&1)*8;
    const int koffA  = ((lane>>4)&1)*4;
    const int mr = 32*mg;
    uint32_t aA[2];
    aA[0] = hbb[0] + (uint32_t)(((mr + rowoff)*HSW + koffA)*4);
    aA[1] = hbb[1] + (uint32_t)(((mr + rowoff)*HSW + koffA)*4);
    uint32_t bA[2];
    {
        int kh = (lane>>3)&1;
        #pragma unroll
        for (int nt=0;nt<2;nt++)
            bA[nt] = sbase + (uint32_t)((((2*ng+nt)*8 + (lane&7))*KPW + kh*4)*4);
    }

    float cst[4];
    #pragma unroll
    for (int i=0;i<4;i++) cst[i] = 0.f;

    for (int t = 0; t < SS; t++){
        float acc[2][2][4];
        #pragma unroll
        for (int a1=0;a1<2;a1++)
            #pragma unroll
            for (int a2=0;a2<2;a2++)
                #pragma unroll
                for (int a3=0;a3<4;a3++) acc[a1][a2][a3] = 0.f;

        if (t > 0){
            const __nv_bfloat16* hprev = g_hs_bf + (size_t)(t-1)*BB*HH;

            // issue chunk 0
            #pragma unroll
            for (int i=0;i<16;i++){
                int seg = i*256 + tid;
                int row = seg >> 5, s16 = seg & 31;
                cp_async16(hbb[0] + (uint32_t)(row*(HSW*4) + s16*16),
                           hprev + (size_t)row*HH + s16*8);
            }
            cp_commit();

            for (int c = 0; c < NCH; c++){
                if (c+1 < NCH){
                    #pragma unroll
                    for (int i=0;i<16;i++){
                        int seg = i*256 + tid;
                        int row = seg >> 5, s16 = seg & 31;
                        cp_async16(hbb[(c+1)&1] + (uint32_t)(row*(HSW*4) + s16*16),
                                   hprev + (size_t)row*HH + (c+1)*CK + s16*8);
                    }
                    cp_commit();
                    cp_wait1();       // chunk c (and, at c=0, the Gin group) done
                } else {
                    cp_wait0();
                }
                __syncthreads();

                const uint32_t aBase = aA[c&1];
                const uint32_t bOff  = (uint32_t)(c*512);   // c*128 words
                #pragma unroll
                for (int s = 0; s < CK/16; s++){
                    uint32_t a0[4], a1[4], bf0[2], bf1[2];
                    ldsm4(a0, aBase + s*32);
                    ldsm4(a1, aBase + s*32 + 16*HSW*4);
                    ldsm2(bf0, bA[0] + bOff + s*32);
                    ldsm2(bf1, bA[1] + bOff + s*32);
                    mma_bf16(acc[0][0], a0, bf0[0], bf0[1]);
                    mma_bf16(acc[0][1], a0, bf1[0], bf1[1]);
                    mma_bf16(acc[1][0], a1, bf0[0], bf0[1]);
                    mma_bf16(acc[1][1], a1, bf1[0], bf1[1]);
                }
                __syncthreads();
            }
        } else {
            cp_wait0();
            __syncthreads();
        }

        // Epilogue: lane owns unit j for 4 m-rows; Gin read from smem.
        #pragma unroll
        for (int mi=0; mi<4; mi++){
            int mt = mi >> 1, hi = mi & 1;
            int m  = mr + 16*mt + gid + 8*hi;
            const float* gp = GinF + m*GSTR + ng*16 + 2*tig;
            float2 fif = *(const float2*)(gp    );
            float2 fgo = *(const float2*)(gp + 8);
            float iv = acc[mt][0][2*hi+0] + fif.x;
            float fv = acc[mt][0][2*hi+1] + fif.y;
            float gv = acc[mt][1][2*hi+0] + fgo.x;
            float ov = acc[mt][1][2*hi+1] + fgo.y;
            float cv = sigmoidf_(fv)*cst[mi] + sigmoidf_(iv)*tanhf_(gv);
            cst[mi] = cv;
            float hv = sigmoidf_(ov)*tanhf_(cv);
            Stage[m*8 + j] = __float2bfloat16(hv);
        }
        __syncthreads();                 // stage complete; Gin reads done

        // Coalesced h write: one 16B row per thread (tid<128).
        if (tid < 128){
            uint4 v = *(const uint4*)(Stage + tid*8);
            *(uint4*)(g_hs_bf + (size_t)t*BB*HH + (size_t)tid*HH + u0) = v;
        }

        if (t < SS-1){
            // Prefetch Gin for t+1 (independent of other CTAs) before barrier.
            const float* gsrc = g_Gin + (size_t)(t+1)*BB*G4 + ct*32;
            #pragma unroll
            for (int i=0;i<4;i++){
                int seg = i*256 + tid;
                int row = seg >> 3, s16 = seg & 7;
                cp_async16(ginb + (uint32_t)(row*(GSTR*4) + s16*16),
                           gsrc + (size_t)row*G4 + s16*4);
            }
            cp_commit();

            __threadfence();             // release h writes
            __syncthreads();
            if (tid == 0){
                unsigned prev = atomicAdd(&g_bar_count, 1u);
                if (prev == gridDim.x - 1){
                    atomicExch(&g_bar_count, 0u);
                    __threadfence();
                    atomicAdd(&g_bar_gen, 1u);
                } else {
                    unsigned target = gen0 + (unsigned)(t+1);
                    while ((int)(*(volatile unsigned*)&g_bar_gen - target) < 0) {}
                }
                __threadfence();
            }
            __syncthreads();
        }
    }
}

// ---------------------------------------------------------------------------
// Kernel 3: out[b*S+t][:] = valid ? hs[t][b] @ lin_W^T + lin_b : (1, 0)
// ---------------------------------------------------------------------------
__global__ void __launch_bounds__(256) k_output(
    const int* __restrict__ lengths, const float* __restrict__ lin_W,
    const float* __restrict__ lin_b, float* __restrict__ out)
{
    int row = blockIdx.x * 8 + (threadIdx.x >> 5);
    if (row >= MTOT) return;
    int lane = threadIdx.x & 31;
    int b = row >> 7, t = row & 127;
    float2 res;
    if (t < lengths[b]){
        const __nv_bfloat162* h2 =
            (const __nv_bfloat162*)(g_hs_bf + ((size_t)t*BB + b)*HH);
        float s0 = 0.f, s1 = 0.f;
        #pragma unroll 4
        for (int k2 = lane; k2 < HH/2; k2 += 32){
            float2 hv = __bfloat1622float2(h2[k2]);
            s0 += hv.x * lin_W[2*k2]     + hv.y * lin_W[2*k2+1];
            s1 += hv.x * lin_W[HH+2*k2]  + hv.y * lin_W[HH+2*k2+1];
        }
        #pragma unroll
        for (int off = 16; off > 0; off >>= 1){
            s0 += __shfl_down_sync(0xffffffffu, s0, off);
            s1 += __shfl_down_sync(0xffffffffu, s1, off);
        }
        res = make_float2(s0 + lin_b[0], s1 + lin_b[1]);
    } else {
        res = make_float2(1.f, 0.f);
    }
    if (lane == 0) *(float2*)(out + (size_t)row*2) = res;
}

// ---------------------------------------------------------------------------
extern "C" void kernel_launch(void* const* d_in, const int* in_sizes, int n_in,
                              void* d_out, int out_size)
{
    const int*   x       = (const int*)  d_in[0];
    const int*   lengths = (const int*)  d_in[1];
    const float* embW    = (const float*)d_in[2];
    const float* W_ih    = (const float*)d_in[3];
    const float* W_hh    = (const float*)d_in[4];
    const float* b_ih    = (const float*)d_in[5];
    const float* b_hh    = (const float*)d_in[6];
    const float* lin_W   = (const float*)d_in[7];
    const float* lin_b   = (const float*)d_in[8];
    float* out = (float*)d_out;

    cudaFuncSetAttribute(k_lstm, cudaFuncAttributeMaxDynamicSharedMemorySize, SMEM_LSTM);

    dim3 gA(G4/64, MTOT/128);   // 64 x 128 CTAs
    k_input_gemm<<<gA, 256>>>(x, embW, W_ih, b_ih, b_hh);
    k_lstm<<<128, 256, SMEM_LSTM>>>(W_hh);
    k_output<<<(MTOT+7)/8, 256>>>(lengths, lin_W, lin_b, out);
}